// round 8
// baseline (speedup 1.0000x reference)
#include <cuda_runtime.h>
#include <cuda_bf16.h>
#include <cuda_fp8.h>
#include <cstdint>

// Problem constants
#define Bn   4
#define Sn   4096
#define Dn   1024
#define Hn   8
#define Mn   32
#define Wn   16
#define NSn  128
#define GHn  128
#define TEMP 0.6f
#define SIGMA 0.12f
#define ALPHA 6.0f
#define HBS  (Hn * Bn * Sn)

#define SCALE_A 4096.0f
#define SCALE_B 32.0f
#define INV_SCALE (1.0f / (SCALE_A * SCALE_B))

// ---------------- scratch (device globals; no allocations allowed) ----------------
__device__ float g_pool_part[32 * Bn * Dn];
__device__ float g_weights[Hn * Bn * Mn];
__device__ float g_final[HBS];
__device__ float g_densP[2 * HBS];          // two NS-halves of raw density
__device__ float g_densSum[Hn * Bn];
__device__ __align__(16) uint8_t g_Af8[(size_t)Bn * Sn * Dn];   // 16 MB: e4m3 dens*x*4096
__device__ __align__(16) uint8_t g_Bf8[(size_t)Dn * Dn];        // 1 MB: e4m3 Wo^T*32, [n][k]

// ---------------- PTX helpers (compute_100-safe) ----------------
__device__ __forceinline__ uint32_t smem_u32(const void* p) {
    uint32_t a;
    asm("{ .reg .u64 t; cvta.to.shared.u64 t, %1; cvt.u32.u64 %0, t; }" : "=r"(a) : "l"(p));
    return a;
}
#define CP16(dst, src) \
    asm volatile("cp.async.cg.shared.global [%0], [%1], 16;" :: "r"(dst), "l"(src))
#define CP_COMMIT() asm volatile("cp.async.commit_group;" ::: "memory")
#define CP_WAIT(n)  asm volatile("cp.async.wait_group %0;" :: "n"(n) : "memory")

#define LDSM4(r0, r1, r2, r3, addr)                                              \
    asm volatile("ldmatrix.sync.aligned.m8n8.x4.shared.b16 {%0,%1,%2,%3}, [%4];" \
                 : "=r"(r0), "=r"(r1), "=r"(r2), "=r"(r3) : "r"(addr))

#define MMAFP8(C, A, Bf)                                                        \
    asm volatile("mma.sync.aligned.m16n8k32.row.col.f32.e4m3.e4m3.f32 "         \
                 "{%0,%1,%2,%3},{%4,%5,%6,%7},{%8,%9},{%0,%1,%2,%3};\n"         \
                 : "+f"(C[0]), "+f"(C[1]), "+f"(C[2]), "+f"(C[3])               \
                 : "r"(A[0]), "r"(A[1]), "r"(A[2]), "r"(A[3]),                  \
                   "r"(Bf[0]), "r"(Bf[1]))

// pack two floats -> e4m3x2 (low byte = lo)
__device__ __forceinline__ uint16_t f2e4m3x2(float lo, float hi) {
    uint16_t r;
    asm("cvt.rn.satfinite.e4m3x2.f32 %0, %1, %2;" : "=h"(r) : "f"(hi), "f"(lo));
    return r;
}
// fp8 smem swizzle: rows are 64B = 4 chunks of 16B; chunk' = c ^ ((row>>1)&3)
__device__ __forceinline__ uint32_t swz8(int row, int c) {
    return (uint32_t)(row * 64 + ((c ^ ((row >> 1) & 3)) << 4));
}

// ---------------- 1) pooled partial sums over S ----------------
__global__ void pool_kernel(const float* __restrict__ x) {
    int d  = blockIdx.x * 256 + threadIdx.x;
    int sc = blockIdx.y;
    int b  = blockIdx.z;
    const float* xp = x + ((size_t)b * Sn + (size_t)sc * 128) * Dn + d;
    float a0 = 0.f, a1 = 0.f;
#pragma unroll 8
    for (int i = 0; i < 128; i += 2) {
        a0 += xp[(size_t)i * Dn];
        a1 += xp[(size_t)(i + 1) * Dn];
    }
    g_pool_part[(sc * Bn + b) * Dn + d] = a0 + a1;
}

// ---------------- 2) gating MLP -> softmax weights ----------------
__global__ void gate_kernel(const float* __restrict__ W1, const float* __restrict__ b1,
                            const float* __restrict__ W2, const float* __restrict__ b2) {
    int b = blockIdx.x, h = blockIdx.y, t = threadIdx.x;
    __shared__ float sp[Dn];
    __shared__ float sh[GHn];

    for (int i = t; i < Dn; i += 128) {
        float a = 0.f;
#pragma unroll
        for (int c = 0; c < 32; c++) a += g_pool_part[(c * Bn + b) * Dn + i];
        sp[i] = a * (1.0f / (float)Sn);
    }
    __syncthreads();
    {
        float acc = b1[h * GHn + t];
        const float* w1 = W1 + (size_t)h * Dn * GHn + t;
#pragma unroll 4
        for (int d = 0; d < Dn; d++) acc = fmaf(sp[d], w1[(size_t)d * GHn], acc);
        sh[t] = fmaxf(acc, 0.0f);
    }
    __syncthreads();
    if (t < Mn) {
        float l = b2[h * Mn + t];
        const float* w2 = W2 + h * GHn * Mn + t;
#pragma unroll
        for (int g = 0; g < GHn; g++) l = fmaf(sh[g], w2[g * Mn], l);
        l *= (1.0f / TEMP);
        float mx = l;
        for (int o = 16; o; o >>= 1) mx = fmaxf(mx, __shfl_xor_sync(0xffffffffu, mx, o));
        float e = __expf(l - mx);
        float sm = e;
        for (int o = 16; o; o >>= 1) sm += __shfl_xor_sync(0xffffffffu, sm, o);
        g_weights[(h * Bn + b) * Mn + t] = e / sm;
    }
    if (t == 0) g_densSum[h * Bn + b] = 0.f;
}

// ---------------- 3) waves -> gated final_grid ----------------
__global__ void wave_kernel(const float* __restrict__ freqs, const float* __restrict__ amps,
                            const float* __restrict__ phases) {
    int h = blockIdx.y, t = threadIdx.x;
    int s = blockIdx.x * 128 + t;
    __shared__ float sf0[Mn * Wn], sf1[Mn * Wn], sc[Mn * Wn], sa[Mn * Wn];
    __shared__ float sw[Bn * Mn];

    for (int i = t; i < Mn * Wn; i += 128) {
        sf0[i] = freqs[(h * Mn * Wn + i) * 2 + 0];
        sf1[i] = freqs[(h * Mn * Wn + i) * 2 + 1];
        sc[i] = (phases[h * Mn * Wn + i] - 1.5707963267948966f) * 0.15915494309189535f;
        sa[i] = amps[h * Mn * Wn + i];
    }
    sw[t] = g_weights[h * Bn * Mn + t];
    __syncthreads();

    float px = -1.0f + (2.0f / 63.0f) * (float)(s & 63);
    float py = -1.0f + (2.0f / 63.0f) * (float)(s >> 6);

    float fg0 = 0.f, fg1 = 0.f, fg2 = 0.f, fg3 = 0.f;
    for (int m = 0; m < Mn; m++) {
        float acc = 0.f;
#pragma unroll
        for (int w = 0; w < Wn; w++) {
            int i = m * Wn + w;
            float tt = fmaf(px, sf0[i], fmaf(py, sf1[i], sc[i]));
            float fr = tt - floorf(tt);
            acc = fmaf(sa[i], fmaf(-4.0f, fabsf(fr - 0.5f), 1.0f), acc);
        }
        fg0 = fmaf(sw[0 * Mn + m], acc, fg0);
        fg1 = fmaf(sw[1 * Mn + m], acc, fg1);
        fg2 = fmaf(sw[2 * Mn + m], acc, fg2);
        fg3 = fmaf(sw[3 * Mn + m], acc, fg3);
    }
    int base = h * Bn * Sn + s;
    g_final[base + 0 * Sn] = fg0;
    g_final[base + 1 * Sn] = fg1;
    g_final[base + 2 * Sn] = fg2;
    g_final[base + 3 * Sn] = fg3;
}

// ---------------- 4) MC density (NS split across 2 block sets) ----------------
__global__ void density_kernel(const float* __restrict__ noise) {
    int s = blockIdx.x * 256 + threadIdx.x;
    int b = blockIdx.y;
    int h = blockIdx.z >> 1, half = blockIdx.z & 1;
    int hb = h * Bn + b;
    float zb = ALPHA * g_final[hb * Sn + s];
    const float* np_ = noise + ((size_t)hb * NSn + half * 64) * Sn + s;
    float acc = 0.f;
#pragma unroll 16
    for (int ns = 0; ns < 64; ns++) {
        float z = fmaf(ALPHA * SIGMA, np_[(size_t)ns * Sn], zb);
        acc += __fdividef(1.0f, 1.0f + __expf(-z));
    }
    float v = acc * (1.0f / (float)NSn);
    g_densP[half * HBS + hb * Sn + s] = v;

    float r = v;
    for (int o = 16; o; o >>= 1) r += __shfl_xor_sync(0xffffffffu, r, o);
    __shared__ float sred[8];
    if ((threadIdx.x & 31) == 0) sred[threadIdx.x >> 5] = r;
    __syncthreads();
    if (threadIdx.x < 8) {
        float rr = sred[threadIdx.x];
        for (int o = 4; o; o >>= 1) rr += __shfl_xor_sync(0xffu, rr, o);
        if (threadIdx.x == 0) atomicAdd(&g_densSum[hb], rr);
    }
}

// ---------------- 5a) prep A: dens*x*4096 -> e4m3 row-major ----------------
// grid 4096, block 256: thread handles 16 consecutive k of one row
__global__ void prepA_kernel(const float* __restrict__ x) {
    int idx = blockIdx.x * 256 + threadIdx.x;
    int R = idx >> 6;                 // 64 threads per row
    int c0 = (idx & 63) * 16;
    int b = R >> 12, s = R & 4095, h = c0 >> 7;
    int hb = h * Bn + b;
    float sc = (g_densP[hb * Sn + s] + g_densP[HBS + hb * Sn + s]) /
               (g_densSum[hb] + 1e-8f) * SCALE_A;

    const float4* src = (const float4*)(x + (size_t)R * Dn + c0);
    uint16_t p[8];
#pragma unroll
    for (int q = 0; q < 4; q++) {
        float4 v = src[q];
        p[q * 2 + 0] = f2e4m3x2(v.x * sc, v.y * sc);
        p[q * 2 + 1] = f2e4m3x2(v.z * sc, v.w * sc);
    }
    uint4 o;
    o.x = (uint32_t)p[0] | ((uint32_t)p[1] << 16);
    o.y = (uint32_t)p[2] | ((uint32_t)p[3] << 16);
    o.z = (uint32_t)p[4] | ((uint32_t)p[5] << 16);
    o.w = (uint32_t)p[6] | ((uint32_t)p[7] << 16);
    *(uint4*)(g_Af8 + (size_t)R * Dn + c0) = o;
}

// ---------------- 5b) prep B: Wo^T * 32 -> e4m3 [n][k] ----------------
// grid (16, 16), block 256: 64x64 tile
__global__ void prepB_kernel(const float* __restrict__ Wo) {
    __shared__ float tile[64][65];
    int k0 = blockIdx.x * 64, n0 = blockIdx.y * 64;
    int c = threadIdx.x & 63, r0 = threadIdx.x >> 6;
#pragma unroll
    for (int i = 0; i < 16; i++)
        tile[r0 + 4 * i][c] = Wo[(size_t)(k0 + r0 + 4 * i) * Dn + n0 + c];
    __syncthreads();
    int n = threadIdx.x >> 2, kc = (threadIdx.x & 3) * 16;
    uint16_t p[8];
#pragma unroll
    for (int q = 0; q < 8; q++)
        p[q] = f2e4m3x2(tile[kc + 2 * q][n] * SCALE_B, tile[kc + 2 * q + 1][n] * SCALE_B);
    uint4 o;
    o.x = (uint32_t)p[0] | ((uint32_t)p[1] << 16);
    o.y = (uint32_t)p[2] | ((uint32_t)p[3] << 16);
    o.z = (uint32_t)p[4] | ((uint32_t)p[5] << 16);
    o.w = (uint32_t)p[6] | ((uint32_t)p[7] << 16);
    *(uint4*)(g_Bf8 + (size_t)(n0 + n) * Dn + k0 + kc) = o;
}

// ---------------- 5c) FP8 HMMA GEMM: out = (dens*x) @ Wo + x + bo ----------------
// CTA 128x128, BK=64 (fp8 => 64B rows), 6-stage cp.async pipeline (96KB, 2 CTAs/SM),
// 256 thr, 8 warps (2m x 4n), warp tile 64x32, m16n8k32 e4m3, ldmatrix.x4.
// Exactly one commit group per iteration (empty at tail) so CP_WAIT(4) always
// guarantees the consumed stage is complete.
#define NSTG 6
#define NKT  16
#define STAGE_BYTES 16384        // A 8KB + B 8KB
#define GEMM_SMEM   (NSTG * STAGE_BYTES)

__global__ __launch_bounds__(256, 2) void gemm_kernel(const float* __restrict__ x,
                                                      const float* __restrict__ bo,
                                                      float* __restrict__ out) {
    extern __shared__ __align__(16) uint8_t dsm[];
    const uint32_t tiles = smem_u32(dsm);

    const int tid = threadIdx.x;
    const int nb = blockIdx.x, mb = blockIdx.y;
    const int warpId = tid >> 5, lane = tid & 31;
    const int wm = warpId & 1, wn = warpId >> 1;
    const int g = lane >> 2, t4 = lane & 3;

    // loader: thread t -> row t>>1 (128 rows), chunks (t&1)*2, (t&1)*2+1
    const int lrow = tid >> 1, lc = (tid & 1) * 2;
    const uint8_t* Agp = g_Af8 + (size_t)(mb * 128 + lrow) * Dn + lc * 16;
    const uint8_t* Bgp = g_Bf8 + (size_t)(nb * 128 + lrow) * Dn + lc * 16;
    const uint32_t so0 = swz8(lrow, lc), so1 = swz8(lrow, lc + 1);

    auto issue = [&](int kt, int st) {
        uint32_t dA = tiles + st * STAGE_BYTES;
        uint32_t dB = dA + 8192;
        int k0 = kt * 64;
        CP16(dA + so0, Agp + k0);
        CP16(dA + so1, Agp + k0 + 16);
        CP16(dB + so0, Bgp + k0);
        CP16(dB + so1, Bgp + k0 + 16);
        CP_COMMIT();
    };

    // ldmatrix lane-address components
    // A: row = wm*64 + mt*16 + ((lane&7) | ((lane>>3)&1)<<3), chunk = 2*ks + (lane>>4)
    int amB[4], amS[4];
    const int arfrag = (lane & 7) | (((lane >> 3) & 1) << 3);
#pragma unroll
    for (int mt = 0; mt < 4; mt++) {
        int row = wm * 64 + mt * 16 + arfrag;
        amB[mt] = row * 64;
        amS[mt] = (row >> 1) & 3;
    }
    const int ahi = lane >> 4;
    // B: n-row = wn*32 + lane, chunk constant per LDSM
    const int brow = wn * 32 + lane;
    const int bnB = brow * 64, bnS = (brow >> 1) & 3;

    float c_[4][4][4] = {};

    issue(0, 0);
    issue(1, 1);
    issue(2, 2);
    issue(3, 3);
    issue(4, 4);

    int st = 0;
    for (int kt = 0; kt < NKT; kt++) {
        CP_WAIT(4);
        __syncthreads();

        // one group per iteration: real prefetch or empty commit (keeps wait depth exact)
        if (kt + 5 < NKT) {
            int stNext = st + 5;
            if (stNext >= NSTG) stNext -= NSTG;
            issue(kt + 5, stNext);
        } else {
            CP_COMMIT();
        }

        uint32_t aB = tiles + st * STAGE_BYTES;
        uint32_t bB = aB + 8192;

#pragma unroll
        for (int ks = 0; ks < 2; ks++) {           // two k32 slabs per BK=64
            uint32_t af[4][4], blo[4], bhi[4];
#pragma unroll
            for (int mt = 0; mt < 4; mt++)
                LDSM4(af[mt][0], af[mt][1], af[mt][2], af[mt][3],
                      aB + amB[mt] + (((2 * ks + ahi) ^ amS[mt]) << 4));
            LDSM4(blo[0], blo[1], blo[2], blo[3],
                  bB + bnB + (((2 * ks) ^ bnS) << 4));
            LDSM4(bhi[0], bhi[1], bhi[2], bhi[3],
                  bB + bnB + (((2 * ks + 1) ^ bnS) << 4));
#pragma unroll
            for (int mt = 0; mt < 4; mt++)
#pragma unroll
                for (int nt = 0; nt < 4; nt++) {
                    uint32_t bb[2] = {blo[nt], bhi[nt]};
                    MMAFP8(c_[mt][nt], af[mt], bb);
                }
        }

        if (++st == NSTG) st = 0;
    }

    // epilogue: rescale + x + bo
#pragma unroll
    for (int mt = 0; mt < 4; mt++) {
        int r0 = mb * 128 + wm * 64 + mt * 16 + g;
#pragma unroll
        for (int nt = 0; nt < 4; nt++) {
            int cc = nb * 128 + wn * 32 + nt * 8 + 2 * t4;
            float2 bo2 = *(const float2*)(bo + cc);
            float2 x0 = *(const float2*)(x + (size_t)r0 * Dn + cc);
            float2 x1 = *(const float2*)(x + (size_t)(r0 + 8) * Dn + cc);
            float2 o0 = make_float2(fmaf(c_[mt][nt][0], INV_SCALE, x0.x + bo2.x),
                                    fmaf(c_[mt][nt][1], INV_SCALE, x0.y + bo2.y));
            float2 o1 = make_float2(fmaf(c_[mt][nt][2], INV_SCALE, x1.x + bo2.x),
                                    fmaf(c_[mt][nt][3], INV_SCALE, x1.y + bo2.y));
            *(float2*)(out + (size_t)r0 * Dn + cc) = o0;
            *(float2*)(out + (size_t)(r0 + 8) * Dn + cc) = o1;
        }
    }
}

// ---------------- launcher ----------------
extern "C" void kernel_launch(void* const* d_in, const int* in_sizes, int n_in,
                              void* d_out, int out_size) {
    const float* x      = (const float*)d_in[0];
    const float* noise  = (const float*)d_in[1];
    const float* W1     = (const float*)d_in[2];
    const float* b1     = (const float*)d_in[3];
    const float* W2     = (const float*)d_in[4];
    const float* b2     = (const float*)d_in[5];
    const float* freqs  = (const float*)d_in[6];
    const float* amps   = (const float*)d_in[7];
    const float* phases = (const float*)d_in[8];
    const float* Wo     = (const float*)d_in[9];
    const float* bo     = (const float*)d_in[10];
    float* out          = (float*)d_out;

    // idempotent, capture-safe; called unconditionally
    cudaFuncSetAttribute(gemm_kernel, cudaFuncAttributeMaxDynamicSharedMemorySize,
                         GEMM_SMEM);

    pool_kernel<<<dim3(Dn / 256, 32, Bn), 256>>>(x);
    gate_kernel<<<dim3(Bn, Hn), 128>>>(W1, b1, W2, b2);
    wave_kernel<<<dim3(Sn / 128, Hn), 128>>>(freqs, amps, phases);
    prepB_kernel<<<dim3(16, 16), 256>>>(Wo);
    density_kernel<<<dim3(Sn / 256, Bn, Hn * 2), 256>>>(noise);
    prepA_kernel<<<4096, 256>>>(x);
    gemm_kernel<<<dim3(Dn / 128, (Bn * Sn) / 128), 256, GEMM_SMEM>>>(x, bo, out);
}

// round 9
// speedup vs baseline: 1.1099x; 1.1099x over previous
#include <cuda_runtime.h>
#include <cuda_bf16.h>
#include <cuda_fp16.h>
#include <cstdint>

// Problem constants
#define Bn   4
#define Sn   4096
#define Dn   1024
#define Hn   8
#define Mn   32
#define Wn   16
#define NSn  128
#define GHn  128
#define TEMP 0.6f
#define SIGMA 0.12f
#define ALPHA 6.0f
#define HBS  (Hn * Bn * Sn)

#define SCALE_A 4096.0f
#define SCALE_B 32.0f
#define INV_SCALE (1.0f / (SCALE_A * SCALE_B))

// ---------------- scratch (device globals; no allocations allowed) ----------------
__device__ float g_pool_part[32 * Bn * Dn];
__device__ float g_weights[Hn * Bn * Mn];
__device__ float g_final[HBS];
__device__ float g_densP[2 * HBS];          // two NS-halves of raw density
__device__ float g_densSum[Hn * Bn];
__device__ __align__(16) __half g_Ah[(size_t)Bn * Sn * Dn];   // 32 MB: f16 dens*x*4096
__device__ __align__(16) __half g_Bh[(size_t)Dn * Dn];        // 2 MB: f16 Wo^T*32, [n][k]

// ---------------- PTX helpers (compute_100-safe) ----------------
__device__ __forceinline__ uint32_t smem_u32(const void* p) {
    uint32_t a;
    asm("{ .reg .u64 t; cvta.to.shared.u64 t, %1; cvt.u32.u64 %0, t; }" : "=r"(a) : "l"(p));
    return a;
}
#define CP16(dst, src) \
    asm volatile("cp.async.cg.shared.global [%0], [%1], 16;" :: "r"(dst), "l"(src))
#define CP_COMMIT() asm volatile("cp.async.commit_group;" ::: "memory")
#define CP_WAIT(n)  asm volatile("cp.async.wait_group %0;" :: "n"(n) : "memory")

#define LDSM4(r0, r1, r2, r3, addr)                                              \
    asm volatile("ldmatrix.sync.aligned.m8n8.x4.shared.b16 {%0,%1,%2,%3}, [%4];" \
                 : "=r"(r0), "=r"(r1), "=r"(r2), "=r"(r3) : "r"(addr))

// fp16 accumulator MMA: 2x legacy-path rate vs f32 accum, half the C regs
#define MMAF16(C, A, Bf)                                                        \
    asm volatile("mma.sync.aligned.m16n8k16.row.col.f16.f16.f16.f16 "           \
                 "{%0,%1},{%2,%3,%4,%5},{%6,%7},{%0,%1};\n"                     \
                 : "+r"(C[0]), "+r"(C[1])                                       \
                 : "r"(A[0]), "r"(A[1]), "r"(A[2]), "r"(A[3]),                  \
                   "r"(Bf[0]), "r"(Bf[1]))

// ---------------- 1) pooled partial sums over S ----------------
__global__ void pool_kernel(const float* __restrict__ x) {
    int d  = blockIdx.x * 256 + threadIdx.x;
    int sc = blockIdx.y;
    int b  = blockIdx.z;
    const float* xp = x + ((size_t)b * Sn + (size_t)sc * 128) * Dn + d;
    float a0 = 0.f, a1 = 0.f;
#pragma unroll 8
    for (int i = 0; i < 128; i += 2) {
        a0 += xp[(size_t)i * Dn];
        a1 += xp[(size_t)(i + 1) * Dn];
    }
    g_pool_part[(sc * Bn + b) * Dn + d] = a0 + a1;
}

// ---------------- 2) gating MLP -> softmax weights ----------------
__global__ void gate_kernel(const float* __restrict__ W1, const float* __restrict__ b1,
                            const float* __restrict__ W2, const float* __restrict__ b2) {
    int b = blockIdx.x, h = blockIdx.y, t = threadIdx.x;
    __shared__ float sp[Dn];
    __shared__ float sh[GHn];

    for (int i = t; i < Dn; i += 128) {
        float a = 0.f;
#pragma unroll
        for (int c = 0; c < 32; c++) a += g_pool_part[(c * Bn + b) * Dn + i];
        sp[i] = a * (1.0f / (float)Sn);
    }
    __syncthreads();
    {
        float acc = b1[h * GHn + t];
        const float* w1 = W1 + (size_t)h * Dn * GHn + t;
#pragma unroll 4
        for (int d = 0; d < Dn; d++) acc = fmaf(sp[d], w1[(size_t)d * GHn], acc);
        sh[t] = fmaxf(acc, 0.0f);
    }
    __syncthreads();
    if (t < Mn) {
        float l = b2[h * Mn + t];
        const float* w2 = W2 + h * GHn * Mn + t;
#pragma unroll
        for (int g = 0; g < GHn; g++) l = fmaf(sh[g], w2[g * Mn], l);
        l *= (1.0f / TEMP);
        float mx = l;
        for (int o = 16; o; o >>= 1) mx = fmaxf(mx, __shfl_xor_sync(0xffffffffu, mx, o));
        float e = __expf(l - mx);
        float sm = e;
        for (int o = 16; o; o >>= 1) sm += __shfl_xor_sync(0xffffffffu, sm, o);
        g_weights[(h * Bn + b) * Mn + t] = e / sm;
    }
    if (t == 0) g_densSum[h * Bn + b] = 0.f;
}

// ---------------- 3) waves -> gated final_grid ----------------
__global__ void wave_kernel(const float* __restrict__ freqs, const float* __restrict__ amps,
                            const float* __restrict__ phases) {
    int h = blockIdx.y, t = threadIdx.x;
    int s = blockIdx.x * 128 + t;
    __shared__ float sf0[Mn * Wn], sf1[Mn * Wn], sc[Mn * Wn], sa[Mn * Wn];
    __shared__ float sw[Bn * Mn];

    for (int i = t; i < Mn * Wn; i += 128) {
        sf0[i] = freqs[(h * Mn * Wn + i) * 2 + 0];
        sf1[i] = freqs[(h * Mn * Wn + i) * 2 + 1];
        sc[i] = (phases[h * Mn * Wn + i] - 1.5707963267948966f) * 0.15915494309189535f;
        sa[i] = amps[h * Mn * Wn + i];
    }
    sw[t] = g_weights[h * Bn * Mn + t];
    __syncthreads();

    float px = -1.0f + (2.0f / 63.0f) * (float)(s & 63);
    float py = -1.0f + (2.0f / 63.0f) * (float)(s >> 6);

    float fg0 = 0.f, fg1 = 0.f, fg2 = 0.f, fg3 = 0.f;
    for (int m = 0; m < Mn; m++) {
        float acc = 0.f;
#pragma unroll
        for (int w = 0; w < Wn; w++) {
            int i = m * Wn + w;
            float tt = fmaf(px, sf0[i], fmaf(py, sf1[i], sc[i]));
            float fr = tt - floorf(tt);
            acc = fmaf(sa[i], fmaf(-4.0f, fabsf(fr - 0.5f), 1.0f), acc);
        }
        fg0 = fmaf(sw[0 * Mn + m], acc, fg0);
        fg1 = fmaf(sw[1 * Mn + m], acc, fg1);
        fg2 = fmaf(sw[2 * Mn + m], acc, fg2);
        fg3 = fmaf(sw[3 * Mn + m], acc, fg3);
    }
    int base = h * Bn * Sn + s;
    g_final[base + 0 * Sn] = fg0;
    g_final[base + 1 * Sn] = fg1;
    g_final[base + 2 * Sn] = fg2;
    g_final[base + 3 * Sn] = fg3;
}

// ---------------- 4) MC density (NS split across 2 block sets) ----------------
__global__ void density_kernel(const float* __restrict__ noise) {
    int s = blockIdx.x * 256 + threadIdx.x;
    int b = blockIdx.y;
    int h = blockIdx.z >> 1, half = blockIdx.z & 1;
    int hb = h * Bn + b;
    float zb = ALPHA * g_final[hb * Sn + s];
    const float* np_ = noise + ((size_t)hb * NSn + half * 64) * Sn + s;
    float acc = 0.f;
#pragma unroll 16
    for (int ns = 0; ns < 64; ns++) {
        float z = fmaf(ALPHA * SIGMA, np_[(size_t)ns * Sn], zb);
        acc += __fdividef(1.0f, 1.0f + __expf(-z));
    }
    float v = acc * (1.0f / (float)NSn);
    g_densP[half * HBS + hb * Sn + s] = v;

    float r = v;
    for (int o = 16; o; o >>= 1) r += __shfl_xor_sync(0xffffffffu, r, o);
    __shared__ float sred[8];
    if ((threadIdx.x & 31) == 0) sred[threadIdx.x >> 5] = r;
    __syncthreads();
    if (threadIdx.x < 8) {
        float rr = sred[threadIdx.x];
        for (int o = 4; o; o >>= 1) rr += __shfl_xor_sync(0xffu, rr, o);
        if (threadIdx.x == 0) atomicAdd(&g_densSum[hb], rr);
    }
}

// ---------------- 5a) prep A: dens*x*4096 -> f16 row-major ----------------
// grid 8192, block 256 (2 rows per block, 8 cols per thread)
__global__ void prepA_kernel(const float* __restrict__ x) {
    int t = threadIdx.x;
    int R = blockIdx.x * 2 + (t >> 7);
    int c0 = (t & 127) * 8;
    int b = R >> 12, s = R & 4095, h = c0 >> 7;
    int hb = h * Bn + b;
    float sc = (g_densP[hb * Sn + s] + g_densP[HBS + hb * Sn + s]) /
               (g_densSum[hb] + 1e-8f) * SCALE_A;

    const float4* src = (const float4*)(x + (size_t)R * Dn + c0);
    float4 v0 = src[0], v1 = src[1];
    __half2 p0 = __floats2half2_rn(v0.x * sc, v0.y * sc);
    __half2 p1 = __floats2half2_rn(v0.z * sc, v0.w * sc);
    __half2 p2 = __floats2half2_rn(v1.x * sc, v1.y * sc);
    __half2 p3 = __floats2half2_rn(v1.z * sc, v1.w * sc);
    uint4 o;
    o.x = *(uint32_t*)&p0; o.y = *(uint32_t*)&p1;
    o.z = *(uint32_t*)&p2; o.w = *(uint32_t*)&p3;
    *(uint4*)(g_Ah + (size_t)R * Dn + c0) = o;
}

// ---------------- 5b) prep B: Wo^T * 32 -> f16 [n][k] ----------------
// grid (32, 32), block 256
__global__ void prepB_kernel(const float* __restrict__ Wo) {
    __shared__ float tile[32][33];
    int k0 = blockIdx.x * 32, n0 = blockIdx.y * 32;
    int c = threadIdx.x & 31, r0 = threadIdx.x >> 5;
#pragma unroll
    for (int i = 0; i < 4; i++)
        tile[r0 + 8 * i][c] = Wo[(size_t)(k0 + r0 + 8 * i) * Dn + n0 + c];
    __syncthreads();
    int c2 = (threadIdx.x & 15) * 2, r = threadIdx.x >> 4;
#pragma unroll
    for (int i = 0; i < 2; i++) {
        int rr = r + 16 * i;
        __half2 p = __floats2half2_rn(tile[c2][rr] * SCALE_B, tile[c2 + 1][rr] * SCALE_B);
        *(__half2*)(g_Bh + (size_t)(n0 + rr) * Dn + k0 + c2) = p;
    }
}

// ---------------- 5c) HMMA GEMM (f16 accum): out = (dens*x) @ Wo + x + bo ----------
// CTA 128x128, BK=64, 3-stage cp.async pipeline (96KB -> 2 CTAs/SM), 256 thr,
// 8 warps (2m x 4n), warp tile 64x32, m16n8k16.f16, ldmatrix.x4, xor-swizzled smem.
// Exactly ONE commit group per iteration (empty at tail) so CP_WAIT(1) always
// guarantees the consumed stage is complete — fixes R6's latent tail race.
#define NSTG 3
#define NKT  16
#define STAGE_BYTES 32768        // A 16KB + B 16KB
#define GEMM_SMEM   (NSTG * STAGE_BYTES)

__global__ __launch_bounds__(256, 2) void gemm_kernel(const float* __restrict__ x,
                                                      const float* __restrict__ bo,
                                                      float* __restrict__ out) {
    extern __shared__ __align__(16) uint8_t dsm[];
    const uint32_t tiles = smem_u32(dsm);

    const int tid = threadIdx.x;
    const int nb = blockIdx.x, mb = blockIdx.y;
    const int warpId = tid >> 5, lane = tid & 31;
    const int wm = warpId & 1, wn = warpId >> 1;
    const int g = lane >> 2, t4 = lane & 3;

    // loader mapping: 4 rows-of-32 per thread, 16B chunk per row
    const int arow = tid >> 3, acol = tid & 7;
    const __half* Agp = g_Ah + (size_t)(mb * 128 + arow) * Dn + acol * 8;
    const __half* Bgp = g_Bh + (size_t)(nb * 128 + arow) * Dn + acol * 8;

    auto issue = [&](int kt, int st) {
        uint32_t dA = tiles + st * STAGE_BYTES;
        uint32_t dB = dA + 16384;
        int k0 = kt * 64;
#pragma unroll
        for (int p = 0; p < 4; p++) {
            int row = arow + p * 32;
            uint32_t off = row * 128 + ((acol ^ (row & 7)) << 4);
            CP16(dA + off, Agp + (size_t)p * 32 * Dn + k0);
            CP16(dB + off, Bgp + (size_t)p * 32 * Dn + k0);
        }
        CP_COMMIT();
    };

    // ldmatrix per-lane address components (fixed across k)
    int amRB[4], amRK[4];
#pragma unroll
    for (int mt = 0; mt < 4; mt++) {
        int amRow = wm * 64 + mt * 16 + (lane & 15);
        amRB[mt] = amRow * 128;
        amRK[mt] = amRow & 7;
    }
    const int ahi = lane >> 4;                           // A k-chunk high bit
    int bnRB[2], bnRK[2];
    const int nidx = (lane & 7) | ((lane >> 1) & 8);
#pragma unroll
    for (int nt2 = 0; nt2 < 2; nt2++) {
        int bnRow = wn * 32 + nt2 * 16 + nidx;
        bnRB[nt2] = bnRow * 128;
        bnRK[nt2] = bnRow & 7;
    }
    const int bhi = (lane >> 3) & 1;                     // B k-chunk high bit

    uint32_t c_[4][4][2] = {};                           // f16x2 accumulators

    issue(0, 0);
    issue(1, 1);

    int st = 0;
    for (int kt = 0; kt < NKT; kt++) {
        CP_WAIT(1);
        __syncthreads();

        // exactly one commit per iteration (prefetch or empty) keeps wait depth exact
        if (kt + 2 < NKT) {
            int stNext = st + 2;
            if (stNext >= NSTG) stNext -= NSTG;
            issue(kt + 2, stNext);
        } else {
            CP_COMMIT();
        }

        uint32_t aB = tiles + st * STAGE_BYTES;
        uint32_t bB = aB + 16384;

#pragma unroll
        for (int ks = 0; ks < 4; ks++) {
            uint32_t af[4][4], bf[2][4];
            const int cca = 2 * ks + ahi;
            const int ccb = 2 * ks + bhi;
#pragma unroll
            for (int mt = 0; mt < 4; mt++)
                LDSM4(af[mt][0], af[mt][1], af[mt][2], af[mt][3],
                      aB + amRB[mt] + ((cca ^ amRK[mt]) << 4));
#pragma unroll
            for (int nt2 = 0; nt2 < 2; nt2++)
                LDSM4(bf[nt2][0], bf[nt2][1], bf[nt2][2], bf[nt2][3],
                      bB + bnRB[nt2] + ((ccb ^ bnRK[nt2]) << 4));
#pragma unroll
            for (int mt = 0; mt < 4; mt++)
#pragma unroll
                for (int nt = 0; nt < 4; nt++) {
                    uint32_t bb[2] = {bf[nt >> 1][(nt & 1) * 2],
                                      bf[nt >> 1][(nt & 1) * 2 + 1]};
                    MMAF16(c_[mt][nt], af[mt], bb);
                }
        }

        if (++st == NSTG) st = 0;
    }

    // epilogue: unpack f16 accum, rescale, + x + bo
#pragma unroll
    for (int mt = 0; mt < 4; mt++) {
        int r0 = mb * 128 + wm * 64 + mt * 16 + g;
#pragma unroll
        for (int nt = 0; nt < 4; nt++) {
            int cc = nb * 128 + wn * 32 + nt * 8 + 2 * t4;
            float2 bo2 = *(const float2*)(bo + cc);
            float2 x0 = *(const float2*)(x + (size_t)r0 * Dn + cc);
            float2 x1 = *(const float2*)(x + (size_t)(r0 + 8) * Dn + cc);
            float2 v0 = __half22float2(*(__half2*)&c_[mt][nt][0]);
            float2 v1 = __half22float2(*(__half2*)&c_[mt][nt][1]);
            float2 o0 = make_float2(fmaf(v0.x, INV_SCALE, x0.x + bo2.x),
                                    fmaf(v0.y, INV_SCALE, x0.y + bo2.y));
            float2 o1 = make_float2(fmaf(v1.x, INV_SCALE, x1.x + bo2.x),
                                    fmaf(v1.y, INV_SCALE, x1.y + bo2.y));
            *(float2*)(out + (size_t)r0 * Dn + cc) = o0;
            *(float2*)(out + (size_t)(r0 + 8) * Dn + cc) = o1;
        }
    }
}

// ---------------- launcher ----------------
extern "C" void kernel_launch(void* const* d_in, const int* in_sizes, int n_in,
                              void* d_out, int out_size) {
    const float* x      = (const float*)d_in[0];
    const float* noise  = (const float*)d_in[1];
    const float* W1     = (const float*)d_in[2];
    const float* b1     = (const float*)d_in[3];
    const float* W2     = (const float*)d_in[4];
    const float* b2     = (const float*)d_in[5];
    const float* freqs  = (const float*)d_in[6];
    const float* amps   = (const float*)d_in[7];
    const float* phases = (const float*)d_in[8];
    const float* Wo     = (const float*)d_in[9];
    const float* bo     = (const float*)d_in[10];
    float* out          = (float*)d_out;

    // idempotent, capture-safe; called unconditionally
    cudaFuncSetAttribute(gemm_kernel, cudaFuncAttributeMaxDynamicSharedMemorySize,
                         GEMM_SMEM);

    pool_kernel<<<dim3(Dn / 256, 32, Bn), 256>>>(x);
    gate_kernel<<<dim3(Bn, Hn), 128>>>(W1, b1, W2, b2);
    wave_kernel<<<dim3(Sn / 128, Hn), 128>>>(freqs, amps, phases);
    prepB_kernel<<<dim3(32, 32), 256>>>(Wo);
    density_kernel<<<dim3(Sn / 256, Bn, Hn * 2), 256>>>(noise);
    prepA_kernel<<<8192, 256>>>(x);
    gemm_kernel<<<dim3(Dn / 128, (Bn * Sn) / 128), 256, GEMM_SMEM>>>(x, bo, out);
}